// round 15
// baseline (speedup 1.0000x reference)
#include <cuda_runtime.h>
#include <cuda_bf16.h>
#include <cstdint>

// Problem constants
#define BATCH 2
#define SEQ   2048
#define EMB   2048
#define HEADS 16
#define HDIM  128
#define ROWS  (BATCH * SEQ)          // 4096
#define QKV_N (3 * EMB)              // 6144
#define NEG_INF (-__int_as_float(0x7f800000))

// ---------------------------------------------------------------------------
// Scratch (device globals — no allocation allowed)
// ---------------------------------------------------------------------------
__device__ __nv_bfloat16 g_qkvh[(size_t)ROWS * QKV_N];   // qkv hi [4096,6144]
__device__ __nv_bfloat16 g_qkvl[(size_t)ROWS * QKV_N];   // qkv lo
__device__ float g_ctx[(size_t)ROWS * EMB];              // attention output fp32
__device__ int8_t g_a8h[(size_t)ROWS * EMB];             // A int8 hi (x, then ctx)
__device__ int8_t g_a8l[(size_t)ROWS * EMB];             // A int8 lo
__device__ int8_t g_wq8h[(size_t)QKV_N * EMB];           // w_qkv^T int8 hi [6144,2048]
__device__ int8_t g_wq8l[(size_t)QKV_N * EMB];
__device__ int8_t g_wo8h[(size_t)EMB * EMB];             // w_out^T int8 hi [2048,2048]
__device__ int8_t g_wo8l[(size_t)EMB * EMB];
__device__ float g_sA[ROWS];                             // A row scales
__device__ float g_sWq[QKV_N];                           // w_qkv^T row scales
__device__ float g_sWo[EMB];                             // w_out^T row scales

// ---------------------------------------------------------------------------
// Family-wide (sm_103-legal) helpers
// ---------------------------------------------------------------------------
__device__ __forceinline__ uint32_t smem_u32(const void* p) {
    uint32_t a;
    asm("{ .reg .u64 t; cvta.to.shared.u64 t, %1; cvt.u32.u64 %0, t; }"
        : "=r"(a) : "l"(p));
    return a;
}

#define CP_ASYNC16(dst, src) \
    asm volatile("cp.async.cg.shared.global [%0], [%1], 16;" \
        :: "r"(dst), "l"(src))
#define CP_COMMIT() asm volatile("cp.async.commit_group;" ::: "memory")
#define CP_WAIT(N)  asm volatile("cp.async.wait_group %0;" :: "n"(N) : "memory")

__device__ __forceinline__ void ldsm_x4(uint32_t* r, uint32_t addr) {
    asm volatile("ldmatrix.sync.aligned.m8n8.x4.shared.b16 {%0,%1,%2,%3}, [%4];"
        : "=r"(r[0]), "=r"(r[1]), "=r"(r[2]), "=r"(r[3]) : "r"(addr));
}
__device__ __forceinline__ void ldsm_x4t(uint32_t* r, uint32_t addr) {
    asm volatile("ldmatrix.sync.aligned.m8n8.x4.trans.shared.b16 {%0,%1,%2,%3}, [%4];"
        : "=r"(r[0]), "=r"(r[1]), "=r"(r[2]), "=r"(r[3]) : "r"(addr));
}

__device__ __forceinline__ void mma_bf16(float* d, const uint32_t* a,
                                         const uint32_t* b) {
    asm volatile(
        "mma.sync.aligned.m16n8k16.row.col.f32.bf16.bf16.f32 "
        "{%0,%1,%2,%3}, {%4,%5,%6,%7}, {%8,%9}, {%0,%1,%2,%3};"
        : "+f"(d[0]), "+f"(d[1]), "+f"(d[2]), "+f"(d[3])
        : "r"(a[0]), "r"(a[1]), "r"(a[2]), "r"(a[3]), "r"(b[0]), "r"(b[1]));
}

// int8 MMA: m16n8k32, s32 accum (exact)
__device__ __forceinline__ void mma_s8(int* d, const uint32_t* a,
                                       const uint32_t* b) {
    asm volatile(
        "mma.sync.aligned.m16n8k32.row.col.s32.s8.s8.s32 "
        "{%0,%1,%2,%3}, {%4,%5,%6,%7}, {%8,%9}, {%0,%1,%2,%3};"
        : "+r"(d[0]), "+r"(d[1]), "+r"(d[2]), "+r"(d[3])
        : "r"(a[0]), "r"(a[1]), "r"(a[2]), "r"(a[3]), "r"(b[0]), "r"(b[1]));
}

// pack two floats into bf16x2 (hi part) and residual bf16x2 (lo part)
__device__ __forceinline__ void split2(float a, float b, uint32_t& h, uint32_t& l) {
    __nv_bfloat162 h2 = __float22bfloat162_rn(make_float2(a, b));
    float2 hf = __bfloat1622float2(h2);
    __nv_bfloat162 l2 = __float22bfloat162_rn(make_float2(a - hf.x, b - hf.y));
    h = *(uint32_t*)&h2;
    l = *(uint32_t*)&l2;
}

// ---------------------------------------------------------------------------
// Row-wise fixed-point quantization: X[row][0..K) -> int8 hi/lo + scale
// x ~= S[row] * (256*h + l)
// ---------------------------------------------------------------------------
__global__ __launch_bounds__(256) void quant_rows(
    const float* __restrict__ X, int8_t* __restrict__ H, int8_t* __restrict__ L,
    float* __restrict__ S, int K)
{
    __shared__ float red[8];
    __shared__ float s_inv;
    const int row = blockIdx.x;
    const int tid = threadIdx.x;
    const float* xr = X + (size_t)row * K;
    float m = 0.f;
    for (int k = tid; k < K; k += 256) m = fmaxf(m, fabsf(xr[k]));
#pragma unroll
    for (int off = 16; off; off >>= 1)
        m = fmaxf(m, __shfl_xor_sync(0xffffffffu, m, off));
    if ((tid & 31) == 0) red[tid >> 5] = m;
    __syncthreads();
    if (tid == 0) {
        float mm = 0.f;
#pragma unroll
        for (int i = 0; i < 8; i++) mm = fmaxf(mm, red[i]);
        S[row] = mm / 32512.f;
        s_inv = mm > 0.f ? 32512.f / mm : 0.f;
    }
    __syncthreads();
    const float inv = s_inv;
    for (int k = tid; k < K; k += 256) {
        int q = __float2int_rn(xr[k] * inv);
        int h = (q + 128) >> 8;          // h in [-127,127]
        int l = q - (h << 8);            // l in [-128,127]
        H[(size_t)row * K + k] = (int8_t)h;
        L[(size_t)row * K + k] = (int8_t)l;
    }
}

// ---------------------------------------------------------------------------
// Column-wise quant + transpose: W[K][N] fp32 -> H/L as [N][K] int8 + S[N]
// ---------------------------------------------------------------------------
__global__ __launch_bounds__(256) void quant_cols(
    const float* __restrict__ W, int8_t* __restrict__ H, int8_t* __restrict__ L,
    float* __restrict__ S, int K, int N)
{
    __shared__ float tile[32][33];
    __shared__ float invs[32];
    const int n0 = blockIdx.x * 32;
    const int tx = threadIdx.x & 31;
    const int ty = threadIdx.x >> 5;   // 0..7
    // pass 1: column max
    float m = 0.f;
    for (int k = ty; k < K; k += 8)
        m = fmaxf(m, fabsf(W[(size_t)k * N + n0 + tx]));
    tile[ty][tx] = m;
    __syncthreads();
    if (ty == 0) {
        float mm = 0.f;
#pragma unroll
        for (int i = 0; i < 8; i++) mm = fmaxf(mm, tile[i][tx]);
        S[n0 + tx] = mm / 32512.f;
        invs[tx] = mm > 0.f ? 32512.f / mm : 0.f;
    }
    __syncthreads();
    // pass 2: tiled transpose + quantize
    for (int k0 = 0; k0 < K; k0 += 32) {
#pragma unroll
        for (int i = 0; i < 4; i++)
            tile[ty + 8 * i][tx] = W[(size_t)(k0 + ty + 8 * i) * N + n0 + tx];
        __syncthreads();
#pragma unroll
        for (int i = 0; i < 4; i++) {
            int nn = ty + 8 * i;
            float inv = invs[nn];
            int q = __float2int_rn(tile[tx][nn] * inv);
            int h = (q + 128) >> 8;
            int l = q - (h << 8);
            size_t o = (size_t)(n0 + nn) * K + k0 + tx;
            H[o] = (int8_t)h;
            L[o] = (int8_t)l;
        }
        __syncthreads();
    }
}

// ---------------------------------------------------------------------------
// int8 3-term GEMM via mma.sync m16n8k32 (IMMA, exact s32 accum):
//   C[M,N] = sA[m]*sB[n]*(65536*hh + 256*(hl+lh)) ;  A=[M,K], B=[N,K] int8 hi/lo
// CTA 128x64, 8 warps (warp tile 32m x 32n), K-chunk 64 int8 (=2 k32 steps),
// 3-stage cp.async pipeline (72 KB smem), 2 CTAs/SM.
// s8-k32 fragments have identical byte layout to bf16-k16 -> same ldmatrix maps.
// ---------------------------------------------------------------------------
#define GM 128
#define GN 64
#define GKC 64
#define ATILE_B 8192                 // 128 rows * 64 B
#define BTILE_B 4096                 // 64 rows * 64 B
#define STAGE_B (2 * ATILE_B + 2 * BTILE_B)   // 24576
#define NSTAGE 3
#define GEMM_SMEM (NSTAGE * STAGE_B)  // 73728

__device__ __forceinline__ uint32_t swz(int row, int ch) {
    return (uint32_t)(row * 64 + ((ch ^ ((row >> 1) & 3)) << 4));
}

__global__ __launch_bounds__(256, 2) void gemm_s8_kernel(
    const int8_t* __restrict__ Ah, const int8_t* __restrict__ Al,
    const int8_t* __restrict__ Bh, const int8_t* __restrict__ Bl,
    const float* __restrict__ sA, const float* __restrict__ sB,
    float* __restrict__ C, __nv_bfloat16* __restrict__ Ch,
    __nv_bfloat16* __restrict__ Cl, int M, int N, int K)
{
    extern __shared__ char smc[];
    const uint32_t sbase = smem_u32(smc);
    const int tid = threadIdx.x;
    const int lane = tid & 31;
    const int wid = tid >> 5;
    const int wm = wid & 3;          // 4 m-tiles of 32
    const int wn = wid >> 2;         // 2 n-tiles of 32
    const int bn = blockIdx.x * GN;
    const int bm = blockIdx.y * GM;
    const int nchunk = K / GKC;

    const int8_t* gA[2] = { Ah + (size_t)bm * K, Al + (size_t)bm * K };
    const int8_t* gB[2] = { Bh + (size_t)bn * K, Bl + (size_t)bn * K };

    // ldmatrix lane mappings (byte-identical to the validated bf16 kernel)
    int rowA[2];
    rowA[0] = wm * 32 + (lane & 15);
    rowA[1] = rowA[0] + 16;
    const int caBit = lane >> 4;
    int rowB[2];
#pragma unroll
    for (int bi = 0; bi < 2; ++bi)
        rowB[bi] = wn * 32 + bi * 16 + (lane & 7) + ((lane >> 4) << 3);
    const int cbBit = (lane >> 3) & 1;

    int ahh[2][4][4], axx[2][4][4];
#pragma unroll
    for (int mi = 0; mi < 2; ++mi)
#pragma unroll
        for (int ni = 0; ni < 4; ++ni)
#pragma unroll
            for (int j = 0; j < 4; ++j) { ahh[mi][ni][j] = 0; axx[mi][ni][j] = 0; }

    auto load_stage = [&](int st, int kc) {
        uint32_t sb = sbase + st * STAGE_B;
#pragma unroll
        for (int t = 0; t < 2; ++t) {           // A hi/lo: 2 cp per thread each
            const char* g = (const char*)(gA[t] + kc);
            uint32_t tb = sb + t * ATILE_B;
#pragma unroll
            for (int v = 0; v < 2; ++v) {
                int idx = tid + 256 * v;        // 0..511
                int r = idx >> 2;               // row 0..127
                int ch = idx & 3;
                CP_ASYNC16(tb + swz(r, ch), g + (size_t)r * K + ch * 16);
            }
        }
#pragma unroll
        for (int t = 0; t < 2; ++t) {           // B hi/lo: 1 cp per thread each
            const char* g = (const char*)(gB[t] + kc);
            uint32_t tb = sb + 2 * ATILE_B + t * BTILE_B;
            int r = tid >> 2;                   // row 0..63
            int ch = tid & 3;
            CP_ASYNC16(tb + swz(r, ch), g + (size_t)r * K + ch * 16);
        }
    };

    auto compute_stage = [&](int st) {
        uint32_t sb = sbase + st * STAGE_B;
#pragma unroll
        for (int ks = 0; ks < 2; ++ks) {        // two k32 steps per chunk
            uint32_t bh[8], bl[8];
#pragma unroll
            for (int bi = 0; bi < 2; ++bi) {
                uint32_t off = swz(rowB[bi], 2 * ks + cbBit);
                ldsm_x4(&bh[4 * bi], sb + 2 * ATILE_B + off);
                ldsm_x4(&bl[4 * bi], sb + 2 * ATILE_B + BTILE_B + off);
            }
#pragma unroll
            for (int mi = 0; mi < 2; ++mi) {
                uint32_t ah4[4], al4[4];
                uint32_t off = swz(rowA[mi], 2 * ks + caBit);
                ldsm_x4(ah4, sb + off);
                ldsm_x4(al4, sb + ATILE_B + off);
#pragma unroll
                for (int ni = 0; ni < 4; ++ni) {
                    mma_s8(ahh[mi][ni], ah4, &bh[2 * ni]);   // hh -> weight 65536
                    mma_s8(axx[mi][ni], ah4, &bl[2 * ni]);   // hl -> weight 256
                    mma_s8(axx[mi][ni], al4, &bh[2 * ni]);   // lh -> weight 256
                }
            }
        }
    };

    // Prologue: 2 stages in flight
#pragma unroll
    for (int s = 0; s < NSTAGE - 1; ++s) {
        load_stage(s, s * GKC);
        CP_COMMIT();
    }
    // Mainloop: one barrier per chunk; empty commits keep wait counts exact
    for (int c = 0; c < nchunk; ++c) {
        CP_WAIT(NSTAGE - 2);
        __syncthreads();
        int nx = c + NSTAGE - 1;
        if (nx < nchunk) load_stage(nx % NSTAGE, nx * GKC);
        CP_COMMIT();
        compute_stage(c % NSTAGE);
    }

    // Epilogue: dequantize C = sA*sB*(65536*hh + 256*cx)
    const int g = lane >> 2;
    const int t2 = (lane & 3) * 2;
#pragma unroll
    for (int mi = 0; mi < 2; ++mi) {
        int row = bm + wm * 32 + mi * 16 + g;
        float sa0 = sA[row], sa1 = sA[row + 8];
#pragma unroll
        for (int ni = 0; ni < 4; ++ni) {
            int col = bn + wn * 32 + ni * 8 + t2;
            float sb0 = sB[col], sb1 = sB[col + 1];
            float v00 = sa0 * sb0 * (65536.f * (float)ahh[mi][ni][0] + 256.f * (float)axx[mi][ni][0]);
            float v01 = sa0 * sb1 * (65536.f * (float)ahh[mi][ni][1] + 256.f * (float)axx[mi][ni][1]);
            float v10 = sa1 * sb0 * (65536.f * (float)ahh[mi][ni][2] + 256.f * (float)axx[mi][ni][2]);
            float v11 = sa1 * sb1 * (65536.f * (float)ahh[mi][ni][3] + 256.f * (float)axx[mi][ni][3]);
            if (Ch == nullptr) {
                *(float2*)(C + (size_t)row * N + col) = make_float2(v00, v01);
                *(float2*)(C + (size_t)(row + 8) * N + col) = make_float2(v10, v11);
            } else {
                uint32_t h, l;
                split2(v00, v01, h, l);
                *(uint32_t*)(Ch + (size_t)row * N + col) = h;
                *(uint32_t*)(Cl + (size_t)row * N + col) = l;
                split2(v10, v11, h, l);
                *(uint32_t*)(Ch + (size_t)(row + 8) * N + col) = h;
                *(uint32_t*)(Cl + (size_t)(row + 8) * N + col) = l;
            }
        }
    }
}

// ---------------------------------------------------------------------------
// HMMA causal flash attention (bf16 hi/lo 3-term, fp32 accum) — proven R12
// kernel; epilogue now writes fp32 ctx.
// ---------------------------------------------------------------------------
#define ATM 64
#define ATT_TILE 16384              // 64 * 256
#define SQH 0
#define SQL (1 * ATT_TILE)
#define SKH (2 * ATT_TILE)
#define SKL (3 * ATT_TILE)
#define SVH (4 * ATT_TILE)
#define SVL (5 * ATT_TILE)
#define ATT_SMEM (6 * ATT_TILE)     // 98304

__device__ __forceinline__ uint32_t aswz(int r, int ch) {
    return (uint32_t)(r * 256 + ((ch ^ (r & 7)) << 4));
}

__global__ __launch_bounds__(128) void attn_tc_kernel(
    const __nv_bfloat16* __restrict__ qkvh,
    const __nv_bfloat16* __restrict__ qkvl,
    float* __restrict__ ctx)
{
    extern __shared__ char sma[];
    const uint32_t sb = smem_u32(sma);
    const int tid = threadIdx.x;
    const int lane = tid & 31;
    const int wid = tid >> 5;
    const int wbase = wid * 16;
    const int g = lane >> 2;
    const int t2 = (lane & 3) * 2;
    const int qt = (gridDim.x - 1) - blockIdx.x;
    const int bh = blockIdx.y;
    const int b = bh >> 4;
    const int h = bh & 15;
    const int q0 = qt * ATM;

    const size_t GROW = 2 * (size_t)QKV_N;
    const char* qkvh_c = (const char*)qkvh;
    const char* qkvl_c = (const char*)qkvl;
    const size_t offQ = (size_t)h * HDIM * 2;
    const size_t offK = ((size_t)EMB + h * HDIM) * 2;
    const size_t offV = ((size_t)2 * EMB + h * HDIM) * 2;

    auto load_tile = [&](uint32_t sdst, const char* gsrc) {
#pragma unroll
        for (int v = 0; v < 8; ++v) {
            int idx = tid + 128 * v;
            int r = idx >> 4;
            int c = idx & 15;
            CP_ASYNC16(sdst + aswz(r, c), gsrc + (size_t)r * GROW + c * 16);
        }
    };

    {
        const size_t gq = (size_t)(b * SEQ + q0) * GROW + offQ;
        load_tile(sb + SQH, qkvh_c + gq);
        load_tile(sb + SQL, qkvl_c + gq);
        CP_COMMIT();
    }

    float o[16][4];
#pragma unroll
    for (int ni = 0; ni < 16; ++ni)
#pragma unroll
        for (int j = 0; j < 4; ++j) o[ni][j] = 0.f;
    float m0 = NEG_INF, m1 = NEG_INF, l0 = 0.f, l1 = 0.f;
    const float scale = 0.08838834764831845f;

    const int rA = wbase + (lane & 15);
    const int cAbit = lane >> 4;
    const int rB = (lane & 7) + ((lane >> 4) << 3);
    const int cBbit = (lane >> 3) & 1;
    const int rVb = (lane & 7) + (((lane >> 3) & 1) << 3);
    const int cVbit = (lane >> 4) & 1;

    for (int kt = 0; kt <= qt; ++kt) {
        const int k0 = kt * ATM;
        {
            const size_t gr = (size_t)(b * SEQ + k0) * GROW;
            load_tile(sb + SKH, qkvh_c + gr + offK);
            load_tile(sb + SKL, qkvl_c + gr + offK);
            CP_COMMIT();
            load_tile(sb + SVH, qkvh_c + gr + offV);
            load_tile(sb + SVL, qkvl_c + gr + offV);
            CP_COMMIT();
        }
        CP_WAIT(1);
        __syncthreads();

        float s[8][4];
#pragma unroll
        for (int ni = 0; ni < 8; ++ni)
#pragma unroll
            for (int j = 0; j < 4; ++j) s[ni][j] = 0.f;

#pragma unroll
        for (int ks = 0; ks < 8; ++ks) {
            uint32_t qh4[4], ql4[4];
            uint32_t offA = aswz(rA, 2 * ks + cAbit);
            ldsm_x4(qh4, sb + SQH + offA);
            ldsm_x4(ql4, sb + SQL + offA);
            uint32_t kh[16], klo[16];
#pragma unroll
            for (int bi = 0; bi < 4; ++bi) {
                uint32_t offB = aswz(bi * 16 + rB, 2 * ks + cBbit);
                ldsm_x4(&kh[4 * bi], sb + SKH + offB);
                ldsm_x4(&klo[4 * bi], sb + SKL + offB);
            }
#pragma unroll
            for (int ni = 0; ni < 8; ++ni) {
                mma_bf16(s[ni], qh4, &kh[2 * ni]);
                mma_bf16(s[ni], qh4, &klo[2 * ni]);
                mma_bf16(s[ni], ql4, &kh[2 * ni]);
            }
        }

        const bool diag = (kt == qt);
        const int grow0 = q0 + wbase + g;
        float mt0 = NEG_INF, mt1 = NEG_INF;
#pragma unroll
        for (int ni = 0; ni < 8; ++ni) {
            int gcol = k0 + ni * 8 + t2;
#pragma unroll
            for (int e = 0; e < 4; ++e) {
                float v = s[ni][e] * scale;
                if (diag) {
                    int r = grow0 + ((e >> 1) << 3);
                    int cc = gcol + (e & 1);
                    if (cc > r) v = NEG_INF;
                }
                s[ni][e] = v;
            }
            mt0 = fmaxf(mt0, fmaxf(s[ni][0], s[ni][1]));
            mt1 = fmaxf(mt1, fmaxf(s[ni][2], s[ni][3]));
        }
#pragma unroll
        for (int off = 1; off <= 2; off <<= 1) {
            mt0 = fmaxf(mt0, __shfl_xor_sync(0xffffffffu, mt0, off));
            mt1 = fmaxf(mt1, __shfl_xor_sync(0xffffffffu, mt1, off));
        }
        float mn0 = fmaxf(m0, mt0), mn1 = fmaxf(m1, mt1);
        float a0 = __expf(m0 - mn0), a1 = __expf(m1 - mn1);
        float sum0 = 0.f, sum1 = 0.f;
#pragma unroll
        for (int ni = 0; ni < 8; ++ni) {
            s[ni][0] = __expf(s[ni][0] - mn0);
            s[ni][1] = __expf(s[ni][1] - mn0);
            s[ni][2] = __expf(s[ni][2] - mn1);
            s[ni][3] = __expf(s[ni][3] - mn1);
            sum0 += s[ni][0] + s[ni][1];
            sum1 += s[ni][2] + s[ni][3];
        }
#pragma unroll
        for (int off = 1; off <= 2; off <<= 1) {
            sum0 += __shfl_xor_sync(0xffffffffu, sum0, off);
            sum1 += __shfl_xor_sync(0xffffffffu, sum1, off);
        }
        l0 = l0 * a0 + sum0;
        l1 = l1 * a1 + sum1;
        m0 = mn0; m1 = mn1;
#pragma unroll
        for (int ni = 0; ni < 16; ++ni) {
            o[ni][0] *= a0; o[ni][1] *= a0;
            o[ni][2] *= a1; o[ni][3] *= a1;
        }

        uint32_t ph[4][4], pl[4][4];
#pragma unroll
        for (int k2 = 0; k2 < 4; ++k2) {
#pragma unroll
            for (int hf = 0; hf < 2; ++hf) {
                int tI = 2 * k2 + hf;
                split2(s[tI][0], s[tI][1], ph[k2][2 * hf], pl[k2][2 * hf]);
                split2(s[tI][2], s[tI][3], ph[k2][2 * hf + 1], pl[k2][2 * hf + 1]);
            }
        }

        CP_WAIT(0);
        __syncthreads();

#pragma unroll
        for (int k2 = 0; k2 < 4; ++k2) {
#pragma unroll
            for (int dv = 0; dv < 8; ++dv) {
                uint32_t vh4[4], vl4[4];
                uint32_t offV2 = aswz(k2 * 16 + rVb, 2 * dv + cVbit);
                ldsm_x4t(vh4, sb + SVH + offV2);
                ldsm_x4t(vl4, sb + SVL + offV2);
                mma_bf16(o[2 * dv], ph[k2], &vh4[0]);
                mma_bf16(o[2 * dv], ph[k2], &vl4[0]);
                mma_bf16(o[2 * dv], pl[k2], &vh4[0]);
                mma_bf16(o[2 * dv + 1], ph[k2], &vh4[2]);
                mma_bf16(o[2 * dv + 1], ph[k2], &vl4[2]);
                mma_bf16(o[2 * dv + 1], pl[k2], &vh4[2]);
            }
        }
        __syncthreads();
    }

    // epilogue: normalize, write fp32 ctx
    const float inv0 = 1.f / l0;
    const float inv1 = 1.f / l1;
    const int grow = b * SEQ + q0 + wbase + g;
    const int gcol = h * HDIM + t2;
#pragma unroll
    for (int ni = 0; ni < 16; ++ni) {
        int col = gcol + ni * 8;
        *(float2*)(ctx + (size_t)grow * EMB + col) =
            make_float2(o[ni][0] * inv0, o[ni][1] * inv0);
        *(float2*)(ctx + (size_t)(grow + 8) * EMB + col) =
            make_float2(o[ni][2] * inv1, o[ni][3] * inv1);
    }
}

// ---------------------------------------------------------------------------
// Launch
// ---------------------------------------------------------------------------
extern "C" void kernel_launch(void* const* d_in, const int* in_sizes, int n_in,
                              void* d_out, int out_size)
{
    const float* x     = (const float*)d_in[0];
    const float* w_qkv = (const float*)d_in[1];
    const float* w_out = (const float*)d_in[2];
    float* out = (float*)d_out;

    __nv_bfloat16 *qkvh = nullptr, *qkvl = nullptr;
    float *ctx = nullptr, *sA = nullptr, *sWq = nullptr, *sWo = nullptr;
    int8_t *a8h = nullptr, *a8l = nullptr;
    int8_t *wq8h = nullptr, *wq8l = nullptr, *wo8h = nullptr, *wo8l = nullptr;
    cudaGetSymbolAddress((void**)&qkvh, g_qkvh);
    cudaGetSymbolAddress((void**)&qkvl, g_qkvl);
    cudaGetSymbolAddress((void**)&ctx, g_ctx);
    cudaGetSymbolAddress((void**)&a8h, g_a8h);
    cudaGetSymbolAddress((void**)&a8l, g_a8l);
    cudaGetSymbolAddress((void**)&wq8h, g_wq8h);
    cudaGetSymbolAddress((void**)&wq8l, g_wq8l);
    cudaGetSymbolAddress((void**)&wo8h, g_wo8h);
    cudaGetSymbolAddress((void**)&wo8l, g_wo8l);
    cudaGetSymbolAddress((void**)&sA, g_sA);
    cudaGetSymbolAddress((void**)&sWq, g_sWq);
    cudaGetSymbolAddress((void**)&sWo, g_sWo);

    cudaFuncSetAttribute(gemm_s8_kernel,
                         cudaFuncAttributeMaxDynamicSharedMemorySize, GEMM_SMEM);
    cudaFuncSetAttribute(attn_tc_kernel,
                         cudaFuncAttributeMaxDynamicSharedMemorySize, ATT_SMEM);

    // 1) quantize x (rows) and both weights (columns -> transposed int8)
    quant_rows<<<ROWS, 256>>>(x, a8h, a8l, sA, EMB);
    quant_cols<<<QKV_N / 32, 256>>>(w_qkv, wq8h, wq8l, sWq, EMB, QKV_N);
    quant_cols<<<EMB / 32, 256>>>(w_out, wo8h, wo8l, sWo, EMB, EMB);

    // 2) QKV projection (IMMA int8), writes qkv as bf16 hi/lo for attention
    gemm_s8_kernel<<<dim3(QKV_N / GN, ROWS / GM), 256, GEMM_SMEM>>>(
        a8h, a8l, wq8h, wq8l, sA, sWq, nullptr, qkvh, qkvl, ROWS, QKV_N, EMB);

    // 3) Causal flash attention (HMMA bf16) -> fp32 ctx
    attn_tc_kernel<<<dim3(SEQ / ATM, BATCH * HEADS), 128, ATT_SMEM>>>(
        qkvh, qkvl, ctx);

    // 4) quantize ctx rows, then output projection (IMMA int8) -> fp32 out
    quant_rows<<<ROWS, 256>>>(ctx, a8h, a8l, sA, EMB);
    gemm_s8_kernel<<<dim3(EMB / GN, ROWS / GM), 256, GEMM_SMEM>>>(
        a8h, a8l, wo8h, wo8l, sA, sWo, out, nullptr, nullptr, ROWS, EMB, EMB);
}

// round 16
// speedup vs baseline: 2.5818x; 2.5818x over previous
#include <cuda_runtime.h>
#include <cuda_bf16.h>
#include <cuda_fp16.h>
#include <cstdint>

// Problem constants
#define BATCH 2
#define SEQ   2048
#define EMB   2048
#define HEADS 16
#define HDIM  128
#define ROWS  (BATCH * SEQ)          // 4096
#define QKV_N (3 * EMB)              // 6144
#define NEG_INF (-__int_as_float(0x7f800000))

// ---------------------------------------------------------------------------
// Scratch (device globals — no allocation allowed)
// ---------------------------------------------------------------------------
__device__ __nv_bfloat16 g_qkvh[(size_t)ROWS * QKV_N];   // qkv hi [4096,6144]
__device__ __nv_bfloat16 g_qkvl[(size_t)ROWS * QKV_N];   // qkv lo
__device__ __nv_bfloat16 g_ah[(size_t)ROWS * EMB];       // x bf16 hi
__device__ __nv_bfloat16 g_al[(size_t)ROWS * EMB];       // x bf16 lo
__device__ __nv_bfloat16 g_wqkv_h[(size_t)QKV_N * EMB];  // w_qkv^T hi [6144,2048]
__device__ __nv_bfloat16 g_wqkv_l[(size_t)QKV_N * EMB];
__device__ __half g_c16h[(size_t)ROWS * EMB];            // ctx fp16 hi
__device__ __half g_c16l[(size_t)ROWS * EMB];            // ctx fp16 lo
__device__ __half g_wo16[(size_t)EMB * EMB];             // w_out^T fp16 [2048,2048]

// ---------------------------------------------------------------------------
// Family-wide (sm_103-legal) helpers: ldmatrix + mma.sync + cp.async
// ---------------------------------------------------------------------------
__device__ __forceinline__ uint32_t smem_u32(const void* p) {
    uint32_t a;
    asm("{ .reg .u64 t; cvta.to.shared.u64 t, %1; cvt.u32.u64 %0, t; }"
        : "=r"(a) : "l"(p));
    return a;
}

#define CP_ASYNC16(dst, src) \
    asm volatile("cp.async.cg.shared.global [%0], [%1], 16;" \
        :: "r"(dst), "l"(src))
#define CP_COMMIT() asm volatile("cp.async.commit_group;" ::: "memory")
#define CP_WAIT(N)  asm volatile("cp.async.wait_group %0;" :: "n"(N) : "memory")

__device__ __forceinline__ void ldsm_x4(uint32_t* r, uint32_t addr) {
    asm volatile("ldmatrix.sync.aligned.m8n8.x4.shared.b16 {%0,%1,%2,%3}, [%4];"
        : "=r"(r[0]), "=r"(r[1]), "=r"(r[2]), "=r"(r[3]) : "r"(addr));
}
__device__ __forceinline__ void ldsm_x4t(uint32_t* r, uint32_t addr) {
    asm volatile("ldmatrix.sync.aligned.m8n8.x4.trans.shared.b16 {%0,%1,%2,%3}, [%4];"
        : "=r"(r[0]), "=r"(r[1]), "=r"(r[2]), "=r"(r[3]) : "r"(addr));
}

__device__ __forceinline__ void mma_bf16(float* d, const uint32_t* a,
                                         const uint32_t* b) {
    asm volatile(
        "mma.sync.aligned.m16n8k16.row.col.f32.bf16.bf16.f32 "
        "{%0,%1,%2,%3}, {%4,%5,%6,%7}, {%8,%9}, {%0,%1,%2,%3};"
        : "+f"(d[0]), "+f"(d[1]), "+f"(d[2]), "+f"(d[3])
        : "r"(a[0]), "r"(a[1]), "r"(a[2]), "r"(a[3]), "r"(b[0]), "r"(b[1]));
}

__device__ __forceinline__ void mma_f16(float* d, const uint32_t* a,
                                        const uint32_t* b) {
    asm volatile(
        "mma.sync.aligned.m16n8k16.row.col.f32.f16.f16.f32 "
        "{%0,%1,%2,%3}, {%4,%5,%6,%7}, {%8,%9}, {%0,%1,%2,%3};"
        : "+f"(d[0]), "+f"(d[1]), "+f"(d[2]), "+f"(d[3])
        : "r"(a[0]), "r"(a[1]), "r"(a[2]), "r"(a[3]), "r"(b[0]), "r"(b[1]));
}

// pack two floats into bf16x2 hi + residual bf16x2 lo
__device__ __forceinline__ void split2(float a, float b, uint32_t& h, uint32_t& l) {
    __nv_bfloat162 h2 = __float22bfloat162_rn(make_float2(a, b));
    float2 hf = __bfloat1622float2(h2);
    __nv_bfloat162 l2 = __float22bfloat162_rn(make_float2(a - hf.x, b - hf.y));
    h = *(uint32_t*)&h2;
    l = *(uint32_t*)&l2;
}

// pack two floats into fp16x2 hi + residual fp16x2 lo (exact to ~2^-22)
__device__ __forceinline__ void split2h(float a, float b, uint32_t& h, uint32_t& l) {
    __half2 h2 = __floats2half2_rn(a, b);
    float2 hf = __half22float2(h2);
    __half2 l2 = __floats2half2_rn(a - hf.x, b - hf.y);
    h = *(uint32_t*)&h2;
    l = *(uint32_t*)&l2;
}

// ---------------------------------------------------------------------------
// fp32 -> (hi, lo) bf16 split, elementwise (vectorized x4)
// ---------------------------------------------------------------------------
__global__ __launch_bounds__(256) void split_kernel(
    const float* __restrict__ X, __nv_bfloat16* __restrict__ Hi,
    __nv_bfloat16* __restrict__ Lo, int n4)
{
    int i = blockIdx.x * 256 + threadIdx.x;
    if (i >= n4) return;
    float4 v = ((const float4*)X)[i];
    uint32_t h0, l0, h1, l1;
    split2(v.x, v.y, h0, l0);
    split2(v.z, v.w, h1, l1);
    uint32_t* Hp = (uint32_t*)(Hi + 4 * (size_t)i);
    uint32_t* Lp = (uint32_t*)(Lo + 4 * (size_t)i);
    Hp[0] = h0; Hp[1] = h1;
    Lp[0] = l0; Lp[1] = l1;
}

// ---------------------------------------------------------------------------
// fp32 W[K][N] -> bf16 hi/lo W^T[N][K] (tiled transpose)
// ---------------------------------------------------------------------------
__global__ __launch_bounds__(256) void split_transpose_kernel(
    const float* __restrict__ W, __nv_bfloat16* __restrict__ Th,
    __nv_bfloat16* __restrict__ Tl, int K, int N)
{
    __shared__ float t[32][33];
    const int n0 = blockIdx.x * 32;
    const int k0 = blockIdx.y * 32;
    const int tx = threadIdx.x & 31;
    const int ty = threadIdx.x >> 5;   // 0..7
#pragma unroll
    for (int i = 0; i < 4; ++i)
        t[ty + 8 * i][tx] = W[(size_t)(k0 + ty + 8 * i) * N + n0 + tx];
    __syncthreads();
#pragma unroll
    for (int i = 0; i < 4; ++i) {
        float v = t[tx][ty + 8 * i];
        __nv_bfloat16 h = __float2bfloat16(v);
        __nv_bfloat16 l = __float2bfloat16(v - __bfloat162float(h));
        size_t o = (size_t)(n0 + ty + 8 * i) * K + k0 + tx;
        Th[o] = h;
        Tl[o] = l;
    }
}

// ---------------------------------------------------------------------------
// fp32 W[K][N] -> single fp16 W^T[N][K] (tiled transpose)
// ---------------------------------------------------------------------------
__global__ __launch_bounds__(256) void transpose_f16_kernel(
    const float* __restrict__ W, __half* __restrict__ T, int K, int N)
{
    __shared__ float t[32][33];
    const int n0 = blockIdx.x * 32;
    const int k0 = blockIdx.y * 32;
    const int tx = threadIdx.x & 31;
    const int ty = threadIdx.x >> 5;
#pragma unroll
    for (int i = 0; i < 4; ++i)
        t[ty + 8 * i][tx] = W[(size_t)(k0 + ty + 8 * i) * N + n0 + tx];
    __syncthreads();
#pragma unroll
    for (int i = 0; i < 4; ++i)
        T[(size_t)(n0 + ty + 8 * i) * K + k0 + tx] = __float2half(t[tx][ty + 8 * i]);
}

// ---------------------------------------------------------------------------
// bf16 hi/lo 3-term GEMM (HMMA) — proven R13 kernel, QKV only.
// Writes C as bf16 hi/lo. 3-stage cp.async (96 KB), 2 CTAs/SM.
// ---------------------------------------------------------------------------
#define GM 128
#define GN 128
#define GKC 32
#define TILE_B 8192
#define STAGE_B (4 * TILE_B)
#define NSTAGE 3
#define GEMM_SMEM (NSTAGE * STAGE_B)  // 98304

__device__ __forceinline__ uint32_t swz(int row, int ch) {
    return (uint32_t)(row * 64 + ((ch ^ ((row >> 1) & 3)) << 4));
}

__global__ __launch_bounds__(256, 2) void gemm_tc_kernel(
    const __nv_bfloat16* __restrict__ Ah, const __nv_bfloat16* __restrict__ Al,
    const __nv_bfloat16* __restrict__ Bh, const __nv_bfloat16* __restrict__ Bl,
    __nv_bfloat16* __restrict__ Ch, __nv_bfloat16* __restrict__ Cl,
    int M, int N, int K)
{
    extern __shared__ char smc[];
    const uint32_t sbase = smem_u32(smc);
    const int tid = threadIdx.x;
    const int lane = tid & 31;
    const int wid = tid >> 5;
    const int wm = wid & 3;
    const int wn = wid >> 2;
    const int bn = blockIdx.x * GN;
    const int bm = blockIdx.y * GM;
    const int nchunk = K / GKC;

    const __nv_bfloat16* gsrc[4] = {
        Ah + (size_t)bm * K, Al + (size_t)bm * K,
        Bh + (size_t)bn * K, Bl + (size_t)bn * K };

    int rowA[2];
    rowA[0] = wm * 32 + (lane & 15);
    rowA[1] = rowA[0] + 16;
    const int caBit = lane >> 4;
    int rowB[4];
#pragma unroll
    for (int bi = 0; bi < 4; ++bi)
        rowB[bi] = wn * 64 + bi * 16 + (lane & 7) + ((lane >> 4) << 3);
    const int cbBit = (lane >> 3) & 1;

    float acc[2][8][4];
#pragma unroll
    for (int mi = 0; mi < 2; ++mi)
#pragma unroll
        for (int ni = 0; ni < 8; ++ni)
#pragma unroll
            for (int j = 0; j < 4; ++j) acc[mi][ni][j] = 0.f;

    auto load_stage = [&](int st, int kc) {
        uint32_t sb = sbase + st * STAGE_B;
#pragma unroll
        for (int t = 0; t < 4; ++t) {
            uint32_t tb = sb + t * TILE_B;
            const char* g = (const char*)(gsrc[t] + kc);
#pragma unroll
            for (int v = 0; v < 2; ++v) {
                int idx = tid + 256 * v;
                int r = idx >> 2;
                int ch = idx & 3;
                CP_ASYNC16(tb + swz(r, ch), g + (size_t)r * K * 2 + ch * 16);
            }
        }
    };

    auto compute_stage = [&](int st) {
        uint32_t sb = sbase + st * STAGE_B;
#pragma unroll
        for (int ks = 0; ks < 2; ++ks) {
            uint32_t bhf[16], blf[16];
#pragma unroll
            for (int bi = 0; bi < 4; ++bi) {
                uint32_t off = swz(rowB[bi], 2 * ks + cbBit);
                ldsm_x4(&bhf[4 * bi], sb + 2 * TILE_B + off);
                ldsm_x4(&blf[4 * bi], sb + 3 * TILE_B + off);
            }
#pragma unroll
            for (int mi = 0; mi < 2; ++mi) {
                uint32_t ahf[4], alf[4];
                uint32_t off = swz(rowA[mi], 2 * ks + caBit);
                ldsm_x4(ahf, sb + off);
                ldsm_x4(alf, sb + TILE_B + off);
#pragma unroll
                for (int ni = 0; ni < 8; ++ni) {
                    mma_bf16(acc[mi][ni], ahf, &bhf[2 * ni]);
                    mma_bf16(acc[mi][ni], ahf, &blf[2 * ni]);
                    mma_bf16(acc[mi][ni], alf, &bhf[2 * ni]);
                }
            }
        }
    };

#pragma unroll
    for (int s = 0; s < NSTAGE - 1; ++s) {
        load_stage(s, s * GKC);
        CP_COMMIT();
    }
    for (int c = 0; c < nchunk; ++c) {
        CP_WAIT(NSTAGE - 2);
        __syncthreads();
        compute_stage(c % NSTAGE);
        __syncthreads();
        int nx = c + NSTAGE - 1;
        if (nx < nchunk) {
            load_stage(nx % NSTAGE, nx * GKC);
            CP_COMMIT();
        }
    }

    const int g = lane >> 2;
    const int t2 = (lane & 3) * 2;
#pragma unroll
    for (int mi = 0; mi < 2; ++mi)
#pragma unroll
        for (int ni = 0; ni < 8; ++ni) {
            int row = bm + wm * 32 + mi * 16 + g;
            int col = bn + wn * 64 + ni * 8 + t2;
            uint32_t h, l;
            split2(acc[mi][ni][0], acc[mi][ni][1], h, l);
            *(uint32_t*)(Ch + (size_t)row * N + col) = h;
            *(uint32_t*)(Cl + (size_t)row * N + col) = l;
            split2(acc[mi][ni][2], acc[mi][ni][3], h, l);
            *(uint32_t*)(Ch + (size_t)(row + 8) * N + col) = h;
            *(uint32_t*)(Cl + (size_t)(row + 8) * N + col) = l;
        }
}

// ---------------------------------------------------------------------------
// fp16 2-term GEMM (HMMA): C = (Ah+Al) @ B^T, A fp16 hi/lo, B single fp16.
// Same structure as gemm_tc; 3 tiles/stage (24 KB), NSTAGE=3 -> 72 KB, 2 CTA/SM.
// fp32 epilogue. Used for the output projection only.
// ---------------------------------------------------------------------------
#define F16_STAGE_B (3 * TILE_B)                // 24576
#define GEMM16_SMEM (NSTAGE * F16_STAGE_B)      // 73728

__global__ __launch_bounds__(256, 2) void gemm_f16_kernel(
    const __half* __restrict__ Ah, const __half* __restrict__ Al,
    const __half* __restrict__ B, float* __restrict__ C,
    int M, int N, int K)
{
    extern __shared__ char smc[];
    const uint32_t sbase = smem_u32(smc);
    const int tid = threadIdx.x;
    const int lane = tid & 31;
    const int wid = tid >> 5;
    const int wm = wid & 3;
    const int wn = wid >> 2;
    const int bn = blockIdx.x * GN;
    const int bm = blockIdx.y * GM;
    const int nchunk = K / GKC;

    const __half* gsrc[3] = {
        Ah + (size_t)bm * K, Al + (size_t)bm * K, B + (size_t)bn * K };

    int rowA[2];
    rowA[0] = wm * 32 + (lane & 15);
    rowA[1] = rowA[0] + 16;
    const int caBit = lane >> 4;
    int rowB[4];
#pragma unroll
    for (int bi = 0; bi < 4; ++bi)
        rowB[bi] = wn * 64 + bi * 16 + (lane & 7) + ((lane >> 4) << 3);
    const int cbBit = (lane >> 3) & 1;

    float acc[2][8][4];
#pragma unroll
    for (int mi = 0; mi < 2; ++mi)
#pragma unroll
        for (int ni = 0; ni < 8; ++ni)
#pragma unroll
            for (int j = 0; j < 4; ++j) acc[mi][ni][j] = 0.f;

    auto load_stage = [&](int st, int kc) {
        uint32_t sb = sbase + st * F16_STAGE_B;
#pragma unroll
        for (int t = 0; t < 3; ++t) {
            uint32_t tb = sb + t * TILE_B;
            const char* g = (const char*)(gsrc[t] + kc);
#pragma unroll
            for (int v = 0; v < 2; ++v) {
                int idx = tid + 256 * v;
                int r = idx >> 2;
                int ch = idx & 3;
                CP_ASYNC16(tb + swz(r, ch), g + (size_t)r * K * 2 + ch * 16);
            }
        }
    };

    auto compute_stage = [&](int st) {
        uint32_t sb = sbase + st * F16_STAGE_B;
#pragma unroll
        for (int ks = 0; ks < 2; ++ks) {
            uint32_t bhf[16];
#pragma unroll
            for (int bi = 0; bi < 4; ++bi) {
                uint32_t off = swz(rowB[bi], 2 * ks + cbBit);
                ldsm_x4(&bhf[4 * bi], sb + 2 * TILE_B + off);
            }
#pragma unroll
            for (int mi = 0; mi < 2; ++mi) {
                uint32_t ahf[4], alf[4];
                uint32_t off = swz(rowA[mi], 2 * ks + caBit);
                ldsm_x4(ahf, sb + off);
                ldsm_x4(alf, sb + TILE_B + off);
#pragma unroll
                for (int ni = 0; ni < 8; ++ni) {
                    mma_f16(acc[mi][ni], ahf, &bhf[2 * ni]);
                    mma_f16(acc[mi][ni], alf, &bhf[2 * ni]);
                }
            }
        }
    };

#pragma unroll
    for (int s = 0; s < NSTAGE - 1; ++s) {
        load_stage(s, s * GKC);
        CP_COMMIT();
    }
    for (int c = 0; c < nchunk; ++c) {
        CP_WAIT(NSTAGE - 2);
        __syncthreads();
        compute_stage(c % NSTAGE);
        __syncthreads();
        int nx = c + NSTAGE - 1;
        if (nx < nchunk) {
            load_stage(nx % NSTAGE, nx * GKC);
            CP_COMMIT();
        }
    }

    const int g = lane >> 2;
    const int t2 = (lane & 3) * 2;
#pragma unroll
    for (int mi = 0; mi < 2; ++mi)
#pragma unroll
        for (int ni = 0; ni < 8; ++ni) {
            int row = bm + wm * 32 + mi * 16 + g;
            int col = bn + wn * 64 + ni * 8 + t2;
            *(float2*)(C + (size_t)row * N + col) =
                make_float2(acc[mi][ni][0], acc[mi][ni][1]);
            *(float2*)(C + (size_t)(row + 8) * N + col) =
                make_float2(acc[mi][ni][2], acc[mi][ni][3]);
        }
}

// ---------------------------------------------------------------------------
// HMMA causal flash attention (bf16 hi/lo 3-term, fp32 accum) — proven R12
// kernel; epilogue writes ctx as fp16 hi/lo for the fp16 out-projection.
// ---------------------------------------------------------------------------
#define ATM 64
#define ATT_TILE 16384              // 64 * 256
#define SQH 0
#define SQL (1 * ATT_TILE)
#define SKH (2 * ATT_TILE)
#define SKL (3 * ATT_TILE)
#define SVH (4 * ATT_TILE)
#define SVL (5 * ATT_TILE)
#define ATT_SMEM (6 * ATT_TILE)     // 98304

__device__ __forceinline__ uint32_t aswz(int r, int ch) {
    return (uint32_t)(r * 256 + ((ch ^ (r & 7)) << 4));
}

__global__ __launch_bounds__(128) void attn_tc_kernel(
    const __nv_bfloat16* __restrict__ qkvh,
    const __nv_bfloat16* __restrict__ qkvl,
    __half* __restrict__ ch, __half* __restrict__ cl)
{
    extern __shared__ char sma[];
    const uint32_t sb = smem_u32(sma);
    const int tid = threadIdx.x;
    const int lane = tid & 31;
    const int wid = tid >> 5;
    const int wbase = wid * 16;
    const int g = lane >> 2;
    const int t2 = (lane & 3) * 2;
    const int qt = (gridDim.x - 1) - blockIdx.x;
    const int bh = blockIdx.y;
    const int b = bh >> 4;
    const int h = bh & 15;
    const int q0 = qt * ATM;

    const size_t GROW = 2 * (size_t)QKV_N;
    const char* qkvh_c = (const char*)qkvh;
    const char* qkvl_c = (const char*)qkvl;
    const size_t offQ = (size_t)h * HDIM * 2;
    const size_t offK = ((size_t)EMB + h * HDIM) * 2;
    const size_t offV = ((size_t)2 * EMB + h * HDIM) * 2;

    auto load_tile = [&](uint32_t sdst, const char* gsrc) {
#pragma unroll
        for (int v = 0; v < 8; ++v) {
            int idx = tid + 128 * v;
            int r = idx >> 4;
            int c = idx & 15;
            CP_ASYNC16(sdst + aswz(r, c), gsrc + (size_t)r * GROW + c * 16);
        }
    };

    {
        const size_t gq = (size_t)(b * SEQ + q0) * GROW + offQ;
        load_tile(sb + SQH, qkvh_c + gq);
        load_tile(sb + SQL, qkvl_c + gq);
        CP_COMMIT();
    }

    float o[16][4];
#pragma unroll
    for (int ni = 0; ni < 16; ++ni)
#pragma unroll
        for (int j = 0; j < 4; ++j) o[ni][j] = 0.f;
    float m0 = NEG_INF, m1 = NEG_INF, l0 = 0.f, l1 = 0.f;
    const float scale = 0.08838834764831845f;

    const int rA = wbase + (lane & 15);
    const int cAbit = lane >> 4;
    const int rB = (lane & 7) + ((lane >> 4) << 3);
    const int cBbit = (lane >> 3) & 1;
    const int rVb = (lane & 7) + (((lane >> 3) & 1) << 3);
    const int cVbit = (lane >> 4) & 1;

    for (int kt = 0; kt <= qt; ++kt) {
        const int k0 = kt * ATM;
        {
            const size_t gr = (size_t)(b * SEQ + k0) * GROW;
            load_tile(sb + SKH, qkvh_c + gr + offK);
            load_tile(sb + SKL, qkvl_c + gr + offK);
            CP_COMMIT();
            load_tile(sb + SVH, qkvh_c + gr + offV);
            load_tile(sb + SVL, qkvl_c + gr + offV);
            CP_COMMIT();
        }
        CP_WAIT(1);
        __syncthreads();

        float s[8][4];
#pragma unroll
        for (int ni = 0; ni < 8; ++ni)
#pragma unroll
            for (int j = 0; j < 4; ++j) s[ni][j] = 0.f;

#pragma unroll
        for (int ks = 0; ks < 8; ++ks) {
            uint32_t qh4[4], ql4[4];
            uint32_t offA = aswz(rA, 2 * ks + cAbit);
            ldsm_x4(qh4, sb + SQH + offA);
            ldsm_x4(ql4, sb + SQL + offA);
            uint32_t kh[16], klo[16];
#pragma unroll
            for (int bi = 0; bi < 4; ++bi) {
                uint32_t offB = aswz(bi * 16 + rB, 2 * ks + cBbit);
                ldsm_x4(&kh[4 * bi], sb + SKH + offB);
                ldsm_x4(&klo[4 * bi], sb + SKL + offB);
            }
#pragma unroll
            for (int ni = 0; ni < 8; ++ni) {
                mma_bf16(s[ni], qh4, &kh[2 * ni]);
                mma_bf16(s[ni], qh4, &klo[2 * ni]);
                mma_bf16(s[ni], ql4, &kh[2 * ni]);
            }
        }

        const bool diag = (kt == qt);
        const int grow0 = q0 + wbase + g;
        float mt0 = NEG_INF, mt1 = NEG_INF;
#pragma unroll
        for (int ni = 0; ni < 8; ++ni) {
            int gcol = k0 + ni * 8 + t2;
#pragma unroll
            for (int e = 0; e < 4; ++e) {
                float v = s[ni][e] * scale;
                if (diag) {
                    int r = grow0 + ((e >> 1) << 3);
                    int cc = gcol + (e & 1);
                    if (cc > r) v = NEG_INF;
                }
                s[ni][e] = v;
            }
            mt0 = fmaxf(mt0, fmaxf(s[ni][0], s[ni][1]));
            mt1 = fmaxf(mt1, fmaxf(s[ni][2], s[ni][3]));
        }
#pragma unroll
        for (int off = 1; off <= 2; off <<= 1) {
            mt0 = fmaxf(mt0, __shfl_xor_sync(0xffffffffu, mt0, off));
            mt1 = fmaxf(mt1, __shfl_xor_sync(0xffffffffu, mt1, off));
        }
        float mn0 = fmaxf(m0, mt0), mn1 = fmaxf(m1, mt1);
        float a0 = __expf(m0 - mn0), a1 = __expf(m1 - mn1);
        float sum0 = 0.f, sum1 = 0.f;
#pragma unroll
        for (int ni = 0; ni < 8; ++ni) {
            s[ni][0] = __expf(s[ni][0] - mn0);
            s[ni][1] = __expf(s[ni][1] - mn0);
            s[ni][2] = __expf(s[ni][2] - mn1);
            s[ni][3] = __expf(s[ni][3] - mn1);
            sum0 += s[ni][0] + s[ni][1];
            sum1 += s[ni][2] + s[ni][3];
        }
#pragma unroll
        for (int off = 1; off <= 2; off <<= 1) {
            sum0 += __shfl_xor_sync(0xffffffffu, sum0, off);
            sum1 += __shfl_xor_sync(0xffffffffu, sum1, off);
        }
        l0 = l0 * a0 + sum0;
        l1 = l1 * a1 + sum1;
        m0 = mn0; m1 = mn1;
#pragma unroll
        for (int ni = 0; ni < 16; ++ni) {
            o[ni][0] *= a0; o[ni][1] *= a0;
            o[ni][2] *= a1; o[ni][3] *= a1;
        }

        uint32_t ph[4][4], pl[4][4];
#pragma unroll
        for (int k2 = 0; k2 < 4; ++k2) {
#pragma unroll
            for (int hf = 0; hf < 2; ++hf) {
                int tI = 2 * k2 + hf;
                split2(s[tI][0], s[tI][1], ph[k2][2 * hf], pl[k2][2 * hf]);
                split2(s[tI][2], s[tI][3], ph[k2][2 * hf + 1], pl[k2][2 * hf + 1]);
            }
        }

        CP_WAIT(0);
        __syncthreads();

#pragma unroll
        for (int k2 = 0; k2 < 4; ++k2) {
#pragma unroll
            for (int dv = 0; dv < 8; ++dv) {
                uint32_t vh4[4], vl4[4];
                uint32_t offV2 = aswz(k2 * 16 + rVb, 2 * dv + cVbit);
                ldsm_x4t(vh4, sb + SVH + offV2);
                ldsm_x4t(vl4, sb + SVL + offV2);
                mma_bf16(o[2 * dv], ph[k2], &vh4[0]);
                mma_bf16(o[2 * dv], ph[k2], &vl4[0]);
                mma_bf16(o[2 * dv], pl[k2], &vh4[0]);
                mma_bf16(o[2 * dv + 1], ph[k2], &vh4[2]);
                mma_bf16(o[2 * dv + 1], ph[k2], &vl4[2]);
                mma_bf16(o[2 * dv + 1], pl[k2], &vh4[2]);
            }
        }
        __syncthreads();
    }

    // ---- epilogue: normalize, write ctx as fp16 hi/lo ----
    const float inv0 = 1.f / l0;
    const float inv1 = 1.f / l1;
    const int grow = b * SEQ + q0 + wbase + g;
    const int gcol = h * HDIM + t2;
#pragma unroll
    for (int ni = 0; ni < 16; ++ni) {
        uint32_t hh, ll;
        int col = gcol + ni * 8;
        split2h(o[ni][0] * inv0, o[ni][1] * inv0, hh, ll);
        *(uint32_t*)(ch + (size_t)grow * EMB + col) = hh;
        *(uint32_t*)(cl + (size_t)grow * EMB + col) = ll;
        split2h(o[ni][2] * inv1, o[ni][3] * inv1, hh, ll);
        *(uint32_t*)(ch + (size_t)(grow + 8) * EMB + col) = hh;
        *(uint32_t*)(cl + (size_t)(grow + 8) * EMB + col) = ll;
    }
}

// ---------------------------------------------------------------------------
// Launch
// ---------------------------------------------------------------------------
extern "C" void kernel_launch(void* const* d_in, const int* in_sizes, int n_in,
                              void* d_out, int out_size)
{
    const float* x     = (const float*)d_in[0];
    const float* w_qkv = (const float*)d_in[1];
    const float* w_out = (const float*)d_in[2];
    float* out = (float*)d_out;

    __nv_bfloat16 *qkvh = nullptr, *qkvl = nullptr, *ah = nullptr, *al = nullptr;
    __nv_bfloat16 *wqh = nullptr, *wql = nullptr;
    __half *c16h = nullptr, *c16l = nullptr, *wo16 = nullptr;
    cudaGetSymbolAddress((void**)&qkvh, g_qkvh);
    cudaGetSymbolAddress((void**)&qkvl, g_qkvl);
    cudaGetSymbolAddress((void**)&ah, g_ah);
    cudaGetSymbolAddress((void**)&al, g_al);
    cudaGetSymbolAddress((void**)&wqh, g_wqkv_h);
    cudaGetSymbolAddress((void**)&wql, g_wqkv_l);
    cudaGetSymbolAddress((void**)&c16h, g_c16h);
    cudaGetSymbolAddress((void**)&c16l, g_c16l);
    cudaGetSymbolAddress((void**)&wo16, g_wo16);

    cudaFuncSetAttribute(gemm_tc_kernel,
                         cudaFuncAttributeMaxDynamicSharedMemorySize, GEMM_SMEM);
    cudaFuncSetAttribute(gemm_f16_kernel,
                         cudaFuncAttributeMaxDynamicSharedMemorySize, GEMM16_SMEM);
    cudaFuncSetAttribute(attn_tc_kernel,
                         cudaFuncAttributeMaxDynamicSharedMemorySize, ATT_SMEM);

    const int n4 = ROWS * EMB / 4;

    // 1) split x -> bf16 hi/lo; prep weights (bf16 hi/lo for QKV, fp16 for out)
    split_kernel<<<(n4 + 255) / 256, 256>>>(x, ah, al, n4);
    split_transpose_kernel<<<dim3(QKV_N / 32, EMB / 32), 256>>>(w_qkv, wqh, wql, EMB, QKV_N);
    transpose_f16_kernel<<<dim3(EMB / 32, EMB / 32), 256>>>(w_out, wo16, EMB, EMB);

    // 2) QKV projection (bf16 3-term HMMA) -> qkv bf16 hi/lo
    gemm_tc_kernel<<<dim3(QKV_N / GN, ROWS / GM), 256, GEMM_SMEM>>>(
        ah, al, wqh, wql, qkvh, qkvl, ROWS, QKV_N, EMB);

    // 3) Causal flash attention (bf16 3-term HMMA) -> ctx fp16 hi/lo
    attn_tc_kernel<<<dim3(SEQ / ATM, BATCH * HEADS), 128, ATT_SMEM>>>(
        qkvh, qkvl, c16h, c16l);

    // 4) Output projection (fp16 2-term HMMA) -> fp32 out
    gemm_f16_kernel<<<dim3(EMB / GN, ROWS / GM), 256, GEMM16_SMEM>>>(
        c16h, c16l, wo16, out, ROWS, EMB, EMB);
}

// round 17
// speedup vs baseline: 3.8091x; 1.4754x over previous
#include <cuda_runtime.h>
#include <cuda_bf16.h>
#include <cstdint>

// Problem constants
#define BATCH 2
#define SEQ   2048
#define EMB   2048
#define HEADS 16
#define HDIM  128
#define ROWS  (BATCH * SEQ)          // 4096
#define QKV_N (3 * EMB)              // 6144
#define NEG_INF (-__int_as_float(0x7f800000))

// ---------------------------------------------------------------------------
// Scratch (device globals — no allocation allowed)
// ---------------------------------------------------------------------------
__device__ __nv_bfloat16 g_qkvh[(size_t)ROWS * QKV_N];   // qkv hi [4096,6144]
__device__ __nv_bfloat16 g_qkvl[(size_t)ROWS * QKV_N];   // qkv lo
__device__ __nv_bfloat16 g_ah[(size_t)ROWS * EMB];       // A hi (x, then ctx)
__device__ __nv_bfloat16 g_al[(size_t)ROWS * EMB];       // A lo
__device__ __nv_bfloat16 g_wqkv_h[(size_t)QKV_N * EMB];  // w_qkv^T hi [6144,2048]
__device__ __nv_bfloat16 g_wqkv_l[(size_t)QKV_N * EMB];
__device__ __nv_bfloat16 g_wout_h[(size_t)EMB * EMB];    // w_out^T hi [2048,2048]
__device__ __nv_bfloat16 g_wout_l[(size_t)EMB * EMB];

// ---------------------------------------------------------------------------
// Family-wide (sm_103-legal) helpers: ldmatrix + mma.sync + cp.async
// ---------------------------------------------------------------------------
__device__ __forceinline__ uint32_t smem_u32(const void* p) {
    uint32_t a;
    asm("{ .reg .u64 t; cvta.to.shared.u64 t, %1; cvt.u32.u64 %0, t; }"
        : "=r"(a) : "l"(p));
    return a;
}

#define CP_ASYNC16(dst, src) \
    asm volatile("cp.async.cg.shared.global [%0], [%1], 16;" \
        :: "r"(dst), "l"(src))
#define CP_COMMIT() asm volatile("cp.async.commit_group;" ::: "memory")
#define CP_WAIT(N)  asm volatile("cp.async.wait_group %0;" :: "n"(N) : "memory")

__device__ __forceinline__ void ldsm_x4(uint32_t* r, uint32_t addr) {
    asm volatile("ldmatrix.sync.aligned.m8n8.x4.shared.b16 {%0,%1,%2,%3}, [%4];"
        : "=r"(r[0]), "=r"(r[1]), "=r"(r[2]), "=r"(r[3]) : "r"(addr));
}
__device__ __forceinline__ void ldsm_x4t(uint32_t* r, uint32_t addr) {
    asm volatile("ldmatrix.sync.aligned.m8n8.x4.trans.shared.b16 {%0,%1,%2,%3}, [%4];"
        : "=r"(r[0]), "=r"(r[1]), "=r"(r[2]), "=r"(r[3]) : "r"(addr));
}

__device__ __forceinline__ void mma_bf16(float* d, const uint32_t* a,
                                         const uint32_t* b) {
    asm volatile(
        "mma.sync.aligned.m16n8k16.row.col.f32.bf16.bf16.f32 "
        "{%0,%1,%2,%3}, {%4,%5,%6,%7}, {%8,%9}, {%0,%1,%2,%3};"
        : "+f"(d[0]), "+f"(d[1]), "+f"(d[2]), "+f"(d[3])
        : "r"(a[0]), "r"(a[1]), "r"(a[2]), "r"(a[3]), "r"(b[0]), "r"(b[1]));
}

// pack two floats into bf16x2 hi + residual bf16x2 lo
__device__ __forceinline__ void split2(float a, float b, uint32_t& h, uint32_t& l) {
    __nv_bfloat162 h2 = __float22bfloat162_rn(make_float2(a, b));
    float2 hf = __bfloat1622float2(h2);
    __nv_bfloat162 l2 = __float22bfloat162_rn(make_float2(a - hf.x, b - hf.y));
    h = *(uint32_t*)&h2;
    l = *(uint32_t*)&l2;
}

// ---------------------------------------------------------------------------
// fp32 -> (hi, lo) bf16 split, elementwise (vectorized x4)
// ---------------------------------------------------------------------------
__global__ __launch_bounds__(256) void split_kernel(
    const float* __restrict__ X, __nv_bfloat16* __restrict__ Hi,
    __nv_bfloat16* __restrict__ Lo, int n4)
{
    int i = blockIdx.x * 256 + threadIdx.x;
    if (i >= n4) return;
    float4 v = ((const float4*)X)[i];
    uint32_t h0, l0, h1, l1;
    split2(v.x, v.y, h0, l0);
    split2(v.z, v.w, h1, l1);
    uint32_t* Hp = (uint32_t*)(Hi + 4 * (size_t)i);
    uint32_t* Lp = (uint32_t*)(Lo + 4 * (size_t)i);
    Hp[0] = h0; Hp[1] = h1;
    Lp[0] = l0; Lp[1] = l1;
}

// ---------------------------------------------------------------------------
// fp32 W[K][N] -> bf16 hi/lo W^T[N][K] (tiled transpose)
// ---------------------------------------------------------------------------
__global__ __launch_bounds__(256) void split_transpose_kernel(
    const float* __restrict__ W, __nv_bfloat16* __restrict__ Th,
    __nv_bfloat16* __restrict__ Tl, int K, int N)
{
    __shared__ float t[32][33];
    const int n0 = blockIdx.x * 32;
    const int k0 = blockIdx.y * 32;
    const int tx = threadIdx.x & 31;
    const int ty = threadIdx.x >> 5;   // 0..7
#pragma unroll
    for (int i = 0; i < 4; ++i)
        t[ty + 8 * i][tx] = W[(size_t)(k0 + ty + 8 * i) * N + n0 + tx];
    __syncthreads();
#pragma unroll
    for (int i = 0; i < 4; ++i) {
        float v = t[tx][ty + 8 * i];
        __nv_bfloat16 h = __float2bfloat16(v);
        __nv_bfloat16 l = __float2bfloat16(v - __bfloat162float(h));
        size_t o = (size_t)(n0 + ty + 8 * i) * K + k0 + tx;
        Th[o] = h;
        Tl[o] = l;
    }
}

// ---------------------------------------------------------------------------
// bf16 hi/lo 3-term GEMM via mma.sync (HMMA), epilogue fp32 OR bf16 hi/lo
// 3-stage cp.async pipeline (96 KB smem), 2 CTAs/SM. R13 loop order with a
// tail-exact wait peel (CP_WAIT(0) on the final chunk) and term-major MMA
// ordering (8 independent accumulators between same-acc reuses).
// ---------------------------------------------------------------------------
#define GM 128
#define GN 128
#define GKC 32
#define TILE_B 8192
#define STAGE_B (4 * TILE_B)
#define NSTAGE 3
#define GEMM_SMEM (NSTAGE * STAGE_B)  // 98304

__device__ __forceinline__ uint32_t swz(int row, int ch) {
    return (uint32_t)(row * 64 + ((ch ^ ((row >> 1) & 3)) << 4));
}

__global__ __launch_bounds__(256, 2) void gemm_tc_kernel(
    const __nv_bfloat16* __restrict__ Ah, const __nv_bfloat16* __restrict__ Al,
    const __nv_bfloat16* __restrict__ Bh, const __nv_bfloat16* __restrict__ Bl,
    float* __restrict__ C, __nv_bfloat16* __restrict__ Ch,
    __nv_bfloat16* __restrict__ Cl, int M, int N, int K)
{
    extern __shared__ char smc[];
    const uint32_t sbase = smem_u32(smc);
    const int tid = threadIdx.x;
    const int lane = tid & 31;
    const int wid = tid >> 5;
    const int wm = wid & 3;
    const int wn = wid >> 2;
    const int bn = blockIdx.x * GN;
    const int bm = blockIdx.y * GM;
    const int nchunk = K / GKC;

    const __nv_bfloat16* gsrc[4] = {
        Ah + (size_t)bm * K, Al + (size_t)bm * K,
        Bh + (size_t)bn * K, Bl + (size_t)bn * K };

    int rowA[2];
    rowA[0] = wm * 32 + (lane & 15);
    rowA[1] = rowA[0] + 16;
    const int caBit = lane >> 4;
    int rowB[4];
#pragma unroll
    for (int bi = 0; bi < 4; ++bi)
        rowB[bi] = wn * 64 + bi * 16 + (lane & 7) + ((lane >> 4) << 3);
    const int cbBit = (lane >> 3) & 1;

    float acc[2][8][4];
#pragma unroll
    for (int mi = 0; mi < 2; ++mi)
#pragma unroll
        for (int ni = 0; ni < 8; ++ni)
#pragma unroll
            for (int j = 0; j < 4; ++j) acc[mi][ni][j] = 0.f;

    auto load_stage = [&](int st, int kc) {
        uint32_t sb = sbase + st * STAGE_B;
#pragma unroll
        for (int t = 0; t < 4; ++t) {
            uint32_t tb = sb + t * TILE_B;
            const char* g = (const char*)(gsrc[t] + kc);
#pragma unroll
            for (int v = 0; v < 2; ++v) {
                int idx = tid + 256 * v;
                int r = idx >> 2;
                int ch = idx & 3;
                CP_ASYNC16(tb + swz(r, ch), g + (size_t)r * K * 2 + ch * 16);
            }
        }
    };

    auto compute_stage = [&](int st) {
        uint32_t sb = sbase + st * STAGE_B;
#pragma unroll
        for (int ks = 0; ks < 2; ++ks) {
            uint32_t bhf[16], blf[16];
#pragma unroll
            for (int bi = 0; bi < 4; ++bi) {
                uint32_t off = swz(rowB[bi], 2 * ks + cbBit);
                ldsm_x4(&bhf[4 * bi], sb + 2 * TILE_B + off);
                ldsm_x4(&blf[4 * bi], sb + 3 * TILE_B + off);
            }
#pragma unroll
            for (int mi = 0; mi < 2; ++mi) {
                uint32_t ahf[4], alf[4];
                uint32_t off = swz(rowA[mi], 2 * ks + caBit);
                ldsm_x4(ahf, sb + off);
                ldsm_x4(alf, sb + TILE_B + off);
                // term-major: 8 independent accumulators between reuses
#pragma unroll
                for (int ni = 0; ni < 8; ++ni)
                    mma_bf16(acc[mi][ni], ahf, &bhf[2 * ni]);
#pragma unroll
                for (int ni = 0; ni < 8; ++ni)
                    mma_bf16(acc[mi][ni], ahf, &blf[2 * ni]);
#pragma unroll
                for (int ni = 0; ni < 8; ++ni)
                    mma_bf16(acc[mi][ni], alf, &bhf[2 * ni]);
            }
        }
    };

#pragma unroll
    for (int s = 0; s < NSTAGE - 1; ++s) {
        load_stage(s, s * GKC);
        CP_COMMIT();
    }
    for (int c = 0; c < nchunk; ++c) {
        if (c + 1 < nchunk) { CP_WAIT(NSTAGE - 2); }   // group g_c done
        else               { CP_WAIT(0); }             // tail-exact: drain all
        __syncthreads();
        compute_stage(c % NSTAGE);
        __syncthreads();
        int nx = c + NSTAGE - 1;
        if (nx < nchunk) {
            load_stage(nx % NSTAGE, nx * GKC);
            CP_COMMIT();
        }
    }

    const int g = lane >> 2;
    const int t2 = (lane & 3) * 2;
    if (Ch == nullptr) {
#pragma unroll
        for (int mi = 0; mi < 2; ++mi)
#pragma unroll
            for (int ni = 0; ni < 8; ++ni) {
                int row = bm + wm * 32 + mi * 16 + g;
                int col = bn + wn * 64 + ni * 8 + t2;
                *(float2*)(C + (size_t)row * N + col) =
                    make_float2(acc[mi][ni][0], acc[mi][ni][1]);
                *(float2*)(C + (size_t)(row + 8) * N + col) =
                    make_float2(acc[mi][ni][2], acc[mi][ni][3]);
            }
    } else {
#pragma unroll
        for (int mi = 0; mi < 2; ++mi)
#pragma unroll
            for (int ni = 0; ni < 8; ++ni) {
                int row = bm + wm * 32 + mi * 16 + g;
                int col = bn + wn * 64 + ni * 8 + t2;
                uint32_t h, l;
                split2(acc[mi][ni][0], acc[mi][ni][1], h, l);
                *(uint32_t*)(Ch + (size_t)row * N + col) = h;
                *(uint32_t*)(Cl + (size_t)row * N + col) = l;
                split2(acc[mi][ni][2], acc[mi][ni][3], h, l);
                *(uint32_t*)(Ch + (size_t)(row + 8) * N + col) = h;
                *(uint32_t*)(Cl + (size_t)(row + 8) * N + col) = l;
            }
    }
}

// ---------------------------------------------------------------------------
// HMMA causal flash attention (bf16 hi/lo 3-term, fp32 accum) — proven R12/R13
// kernel. BM=BN=64, 128 threads (4 warps). Smem: Q/K/V hi+lo tiles, 96 KB.
// K and V committed as separate cp.async groups: V load hidden behind S+softmax.
// ---------------------------------------------------------------------------
#define ATM 64
#define ATT_TILE 16384              // 64 * 256
#define SQH 0
#define SQL (1 * ATT_TILE)
#define SKH (2 * ATT_TILE)
#define SKL (3 * ATT_TILE)
#define SVH (4 * ATT_TILE)
#define SVL (5 * ATT_TILE)
#define ATT_SMEM (6 * ATT_TILE)     // 98304

__device__ __forceinline__ uint32_t aswz(int r, int ch) {
    return (uint32_t)(r * 256 + ((ch ^ (r & 7)) << 4));
}

__global__ __launch_bounds__(128) void attn_tc_kernel(
    const __nv_bfloat16* __restrict__ qkvh,
    const __nv_bfloat16* __restrict__ qkvl,
    __nv_bfloat16* __restrict__ ch, __nv_bfloat16* __restrict__ cl)
{
    extern __shared__ char sma[];
    const uint32_t sb = smem_u32(sma);
    const int tid = threadIdx.x;
    const int lane = tid & 31;
    const int wid = tid >> 5;
    const int wbase = wid * 16;
    const int g = lane >> 2;
    const int t2 = (lane & 3) * 2;
    const int qt = (gridDim.x - 1) - blockIdx.x;  // longest first
    const int bh = blockIdx.y;
    const int b = bh >> 4;
    const int h = bh & 15;
    const int q0 = qt * ATM;

    const size_t GROW = 2 * (size_t)QKV_N;    // gmem row stride, bytes
    const char* qkvh_c = (const char*)qkvh;
    const char* qkvl_c = (const char*)qkvl;
    const size_t offQ = (size_t)h * HDIM * 2;                 // h*256
    const size_t offK = ((size_t)EMB + h * HDIM) * 2;         // 4096 + h*256
    const size_t offV = ((size_t)2 * EMB + h * HDIM) * 2;     // 8192 + h*256

    auto load_tile = [&](uint32_t sdst, const char* gsrc) {
#pragma unroll
        for (int v = 0; v < 8; ++v) {
            int idx = tid + 128 * v;
            int r = idx >> 4;
            int c = idx & 15;
            CP_ASYNC16(sdst + aswz(r, c), gsrc + (size_t)r * GROW + c * 16);
        }
    };

    // Q tiles (hi/lo)
    {
        const size_t gq = (size_t)(b * SEQ + q0) * GROW + offQ;
        load_tile(sb + SQH, qkvh_c + gq);
        load_tile(sb + SQL, qkvl_c + gq);
        CP_COMMIT();
    }

    float o[16][4];
#pragma unroll
    for (int ni = 0; ni < 16; ++ni)
#pragma unroll
        for (int j = 0; j < 4; ++j) o[ni][j] = 0.f;
    float m0 = NEG_INF, m1 = NEG_INF, l0 = 0.f, l1 = 0.f;
    const float scale = 0.08838834764831845f;  // 1/sqrt(128)

    const int rA = wbase + (lane & 15);               // Q rows (A operand)
    const int cAbit = lane >> 4;
    const int rB = (lane & 7) + ((lane >> 4) << 3);   // K rows base (B operand)
    const int cBbit = (lane >> 3) & 1;
    const int rVb = (lane & 7) + (((lane >> 3) & 1) << 3);  // V rows base
    const int cVbit = (lane >> 4) & 1;

    for (int kt = 0; kt <= qt; ++kt) {
        const int k0 = kt * ATM;
        {
            const size_t gr = (size_t)(b * SEQ + k0) * GROW;
            load_tile(sb + SKH, qkvh_c + gr + offK);
            load_tile(sb + SKL, qkvl_c + gr + offK);
            CP_COMMIT();                       // group: K
            load_tile(sb + SVH, qkvh_c + gr + offV);
            load_tile(sb + SVL, qkvl_c + gr + offV);
            CP_COMMIT();                       // group: V
        }
        CP_WAIT(1);        // K (and Q) ready; V may still be in flight
        __syncthreads();

        // ---- S = Q @ K^T (warp: 16 x 64), 3-term compensated ----
        float s[8][4];
#pragma unroll
        for (int ni = 0; ni < 8; ++ni)
#pragma unroll
            for (int j = 0; j < 4; ++j) s[ni][j] = 0.f;

#pragma unroll
        for (int ks = 0; ks < 8; ++ks) {
            uint32_t qh4[4], ql4[4];
            uint32_t offA = aswz(rA, 2 * ks + cAbit);
            ldsm_x4(qh4, sb + SQH + offA);
            ldsm_x4(ql4, sb + SQL + offA);
            uint32_t kh[16], klo[16];
#pragma unroll
            for (int bi = 0; bi < 4; ++bi) {
                uint32_t offB = aswz(bi * 16 + rB, 2 * ks + cBbit);
                ldsm_x4(&kh[4 * bi], sb + SKH + offB);
                ldsm_x4(&klo[4 * bi], sb + SKL + offB);
            }
#pragma unroll
            for (int ni = 0; ni < 8; ++ni)
                mma_bf16(s[ni], qh4, &kh[2 * ni]);
#pragma unroll
            for (int ni = 0; ni < 8; ++ni)
                mma_bf16(s[ni], qh4, &klo[2 * ni]);
#pragma unroll
            for (int ni = 0; ni < 8; ++ni)
                mma_bf16(s[ni], ql4, &kh[2 * ni]);
        }

        // ---- scale + causal mask + online softmax ----
        const bool diag = (kt == qt);
        const int grow0 = q0 + wbase + g;       // rows g, g+8
        float mt0 = NEG_INF, mt1 = NEG_INF;
#pragma unroll
        for (int ni = 0; ni < 8; ++ni) {
            int gcol = k0 + ni * 8 + t2;
#pragma unroll
            for (int e = 0; e < 4; ++e) {
                float v = s[ni][e] * scale;
                if (diag) {
                    int r = grow0 + ((e >> 1) << 3);
                    int cc = gcol + (e & 1);
                    if (cc > r) v = NEG_INF;
                }
                s[ni][e] = v;
            }
            mt0 = fmaxf(mt0, fmaxf(s[ni][0], s[ni][1]));
            mt1 = fmaxf(mt1, fmaxf(s[ni][2], s[ni][3]));
        }
#pragma unroll
        for (int off = 1; off <= 2; off <<= 1) {
            mt0 = fmaxf(mt0, __shfl_xor_sync(0xffffffffu, mt0, off));
            mt1 = fmaxf(mt1, __shfl_xor_sync(0xffffffffu, mt1, off));
        }
        float mn0 = fmaxf(m0, mt0), mn1 = fmaxf(m1, mt1);
        float a0 = __expf(m0 - mn0), a1 = __expf(m1 - mn1);
        float sum0 = 0.f, sum1 = 0.f;
#pragma unroll
        for (int ni = 0; ni < 8; ++ni) {
            s[ni][0] = __expf(s[ni][0] - mn0);
            s[ni][1] = __expf(s[ni][1] - mn0);
            s[ni][2] = __expf(s[ni][2] - mn1);
            s[ni][3] = __expf(s[ni][3] - mn1);
            sum0 += s[ni][0] + s[ni][1];
            sum1 += s[ni][2] + s[ni][3];
        }
#pragma unroll
        for (int off = 1; off <= 2; off <<= 1) {
            sum0 += __shfl_xor_sync(0xffffffffu, sum0, off);
            sum1 += __shfl_xor_sync(0xffffffffu, sum1, off);
        }
        l0 = l0 * a0 + sum0;
        l1 = l1 * a1 + sum1;
        m0 = mn0; m1 = mn1;
#pragma unroll
        for (int ni = 0; ni < 16; ++ni) {
            o[ni][0] *= a0; o[ni][1] *= a0;
            o[ni][2] *= a1; o[ni][3] *= a1;
        }

        // ---- pack P to bf16 hi/lo A-fragments ----
        uint32_t ph[4][4], pl[4][4];
#pragma unroll
        for (int k2 = 0; k2 < 4; ++k2) {
#pragma unroll
            for (int hf = 0; hf < 2; ++hf) {
                int tI = 2 * k2 + hf;
                split2(s[tI][0], s[tI][1], ph[k2][2 * hf], pl[k2][2 * hf]);
                split2(s[tI][2], s[tI][3], ph[k2][2 * hf + 1], pl[k2][2 * hf + 1]);
            }
        }

        CP_WAIT(0);        // V ready
        __syncthreads();

        // ---- O += P @ V (warp: 16 x 128), 3-term compensated ----
#pragma unroll
        for (int k2 = 0; k2 < 4; ++k2) {
#pragma unroll
            for (int dv = 0; dv < 8; ++dv) {
                uint32_t vh4[4], vl4[4];
                uint32_t offV2 = aswz(k2 * 16 + rVb, 2 * dv + cVbit);
                ldsm_x4t(vh4, sb + SVH + offV2);
                ldsm_x4t(vl4, sb + SVL + offV2);
                mma_bf16(o[2 * dv], ph[k2], &vh4[0]);
                mma_bf16(o[2 * dv], ph[k2], &vl4[0]);
                mma_bf16(o[2 * dv], pl[k2], &vh4[0]);
                mma_bf16(o[2 * dv + 1], ph[k2], &vh4[2]);
                mma_bf16(o[2 * dv + 1], ph[k2], &vl4[2]);
                mma_bf16(o[2 * dv + 1], pl[k2], &vh4[2]);
            }
        }
        __syncthreads();   // all warps done with K/V smem before next load
    }

    // ---- epilogue: normalize, write ctx as bf16 hi/lo ----
    const float inv0 = 1.f / l0;
    const float inv1 = 1.f / l1;
    const int grow = b * SEQ + q0 + wbase + g;
    const int gcol = h * HDIM + t2;
#pragma unroll
    for (int ni = 0; ni < 16; ++ni) {
        uint32_t hh, ll;
        int col = gcol + ni * 8;
        split2(o[ni][0] * inv0, o[ni][1] * inv0, hh, ll);
        *(uint32_t*)(ch + (size_t)grow * EMB + col) = hh;
        *(uint32_t*)(cl + (size_t)grow * EMB + col) = ll;
        split2(o[ni][2] * inv1, o[ni][3] * inv1, hh, ll);
        *(uint32_t*)(ch + (size_t)(grow + 8) * EMB + col) = hh;
        *(uint32_t*)(cl + (size_t)(grow + 8) * EMB + col) = ll;
    }
}

// ---------------------------------------------------------------------------
// Launch
// ---------------------------------------------------------------------------
extern "C" void kernel_launch(void* const* d_in, const int* in_sizes, int n_in,
                              void* d_out, int out_size)
{
    const float* x     = (const float*)d_in[0];
    const float* w_qkv = (const float*)d_in[1];
    const float* w_out = (const float*)d_in[2];
    float* out = (float*)d_out;

    __nv_bfloat16 *qkvh = nullptr, *qkvl = nullptr, *ah = nullptr, *al = nullptr;
    __nv_bfloat16 *wqh = nullptr, *wql = nullptr, *woh = nullptr, *wol = nullptr;
    cudaGetSymbolAddress((void**)&qkvh, g_qkvh);
    cudaGetSymbolAddress((void**)&qkvl, g_qkvl);
    cudaGetSymbolAddress((void**)&ah, g_ah);
    cudaGetSymbolAddress((void**)&al, g_al);
    cudaGetSymbolAddress((void**)&wqh, g_wqkv_h);
    cudaGetSymbolAddress((void**)&wql, g_wqkv_l);
    cudaGetSymbolAddress((void**)&woh, g_wout_h);
    cudaGetSymbolAddress((void**)&wol, g_wout_l);

    cudaFuncSetAttribute(gemm_tc_kernel,
                         cudaFuncAttributeMaxDynamicSharedMemorySize, GEMM_SMEM);
    cudaFuncSetAttribute(attn_tc_kernel,
                         cudaFuncAttributeMaxDynamicSharedMemorySize, ATT_SMEM);

    const int n4 = ROWS * EMB / 4;

    // 1) split x -> bf16 hi/lo; split+transpose both weights
    split_kernel<<<(n4 + 255) / 256, 256>>>(x, ah, al, n4);
    split_transpose_kernel<<<dim3(QKV_N / 32, EMB / 32), 256>>>(w_qkv, wqh, wql, EMB, QKV_N);
    split_transpose_kernel<<<dim3(EMB / 32, EMB / 32), 256>>>(w_out, woh, wol, EMB, EMB);

    // 2) QKV projection (bf16 3-term HMMA) -> qkv bf16 hi/lo
    gemm_tc_kernel<<<dim3(QKV_N / GN, ROWS / GM), 256, GEMM_SMEM>>>(
        ah, al, wqh, wql, nullptr, qkvh, qkvl, ROWS, QKV_N, EMB);

    // 3) Causal flash attention (bf16 3-term HMMA) -> ctx bf16 hi/lo (into ah/al)
    attn_tc_kernel<<<dim3(SEQ / ATM, BATCH * HEADS), 128, ATT_SMEM>>>(
        qkvh, qkvl, ah, al);

    // 4) Output projection (bf16 3-term HMMA) -> fp32 out
    gemm_tc_kernel<<<dim3(EMB / GN, ROWS / GM), 256, GEMM_SMEM>>>(
        ah, al, woh, wol, out, nullptr, nullptr, ROWS, EMB, EMB);
}